// round 1
// baseline (speedup 1.0000x reference)
#include <cuda_runtime.h>

// Kalman filter, B=2048, T=64, STATE=32, OBS=16.
// Covariance recursion is batch-independent (cov0 identical across batch),
// so phase 1 computes per-step gain K_t and transition A_t = (I - K_t H) F once,
// and phase 2 runs the cheap per-batch linear recursion x_t = A_t x_{t-1} + K_t z_t.

#define SD 32
#define OD 16
#define TT 64
#define NB 2048
#define BPC 8   // batches per CTA in phase 2

// Per-step precomputed matrices (transposed layouts for conflict-free LDS in phase 2)
__device__ float g_AT[TT][SD * SD];  // g_AT[t][j*32+i] = A_t[i][j]
__device__ float g_KT[TT][OD * SD];  // g_KT[t][o*32+i] = K_t[i][o]

// ---------------------------------------------------------------------------
// Phase 1: single CTA, sequential over T. Computes the shared gain sequence.
// ---------------------------------------------------------------------------
__global__ void __launch_bounds__(768, 1) phase1_kernel(
    const float* __restrict__ Fg,
    const float* __restrict__ Hg,
    const float* __restrict__ Qg,
    const float* __restrict__ Rg,
    const float* __restrict__ cov0)  // first batch's 32x32 covariance
{
    __shared__ float Fs[SD * SD], Hs[OD * SD], Qs[SD * SD], Rs[OD * OD];
    __shared__ float Ps[SD * SD];   // current filtered covariance
    __shared__ float T1[SD * SD];   // temp: F@P, later K@H
    __shared__ float Pp[SD * SD];   // predicted covariance
    __shared__ float HP[OD * SD];   // H @ Pp
    __shared__ float aug[OD][48];   // [S | HP] augmented system -> [I | K^T]

    const int tid = threadIdx.x;

    for (int e = tid; e < SD * SD; e += 768) {
        Fs[e] = Fg[e];
        Qs[e] = Qg[e];
        Ps[e] = cov0[e];
    }
    for (int e = tid; e < OD * SD; e += 768) Hs[e] = Hg[e];
    for (int e = tid; e < OD * OD; e += 768) Rs[e] = Rg[e];
    __syncthreads();

    const int gr = tid / 48;  // 0..15
    const int gc = tid % 48;  // 0..47

    for (int t = 0; t < TT; t++) {
        // --- T1 = F @ P ---
        for (int e = tid; e < SD * SD; e += 768) {
            int i = e >> 5, j = e & 31;
            float a = 0.f;
            #pragma unroll
            for (int k = 0; k < SD; k++) a += Fs[i * SD + k] * Ps[k * SD + j];
            T1[e] = a;
        }
        __syncthreads();

        // --- Pp = T1 @ F^T + Q ---
        for (int e = tid; e < SD * SD; e += 768) {
            int i = e >> 5, j = e & 31;
            float a = Qs[e];
            #pragma unroll
            for (int k = 0; k < SD; k++) a += T1[i * SD + k] * Fs[j * SD + k];
            Pp[e] = a;
        }
        __syncthreads();

        // --- HP = H @ Pp ---
        for (int e = tid; e < OD * SD; e += 768) {
            int o = e >> 5, j = e & 31;
            float a = 0.f;
            #pragma unroll
            for (int k = 0; k < SD; k++) a += Hs[o * SD + k] * Pp[k * SD + j];
            HP[e] = a;
        }
        __syncthreads();

        // --- build augmented [S | HP], S = HP @ H^T + R ---
        {
            float a;
            if (gc < OD) {
                a = Rs[gr * OD + gc];
                #pragma unroll
                for (int k = 0; k < SD; k++) a += HP[gr * SD + k] * Hs[gc * SD + k];
            } else {
                a = HP[gr * SD + (gc - OD)];
            }
            aug[gr][gc] = a;
        }
        __syncthreads();

        // --- Gauss-Jordan: reduce [S | HP] -> [I | K^T]  (S is SPD, no pivoting) ---
        #pragma unroll 1
        for (int p = 0; p < OD; p++) {
            float piv = aug[p][p];
            float pr  = aug[p][gc];
            float cv  = aug[gr][p];
            float cur = aug[gr][gc];
            __syncthreads();
            float prn = pr / piv;
            aug[gr][gc] = (gr == p) ? prn : (cur - cv * prn);
            __syncthreads();
        }
        // Now K[i][o] = aug[o][16+i]

        // --- T1 = K @ H ---
        for (int e = tid; e < SD * SD; e += 768) {
            int i = e >> 5, j = e & 31;
            float a = 0.f;
            #pragma unroll
            for (int o = 0; o < OD; o++) a += aug[o][OD + i] * Hs[o * SD + j];
            T1[e] = a;
        }
        __syncthreads();

        // --- A = F - (KH) @ F   (stored transposed), P_new = Pp - K @ HP ---
        for (int e = tid; e < SD * SD; e += 768) {
            int i = e >> 5, j = e & 31;
            float a = Fs[e];
            #pragma unroll
            for (int k = 0; k < SD; k++) a -= T1[i * SD + k] * Fs[k * SD + j];
            g_AT[t][j * SD + i] = a;  // transposed

            float pn = Pp[e];
            #pragma unroll
            for (int o = 0; o < OD; o++) pn -= aug[o][OD + i] * HP[o * SD + j];
            Ps[e] = pn;
        }
        // --- store K^T ---
        for (int e = tid; e < OD * SD; e += 768) {
            int o = e >> 5, i = e & 31;
            g_KT[t][e] = aug[o][OD + i];
        }
        __syncthreads();
    }
}

// ---------------------------------------------------------------------------
// Phase 2: per-batch linear recursion x_t = A_t x_{t-1} + K_t z_t.
// One warp per batch (lane = state index), 8 batches per CTA.
// ---------------------------------------------------------------------------
__global__ void __launch_bounds__(BPC * 32, 1) phase2_kernel(
    const float* __restrict__ x0,
    const float* __restrict__ meas,  // (B, T, OD)
    float* __restrict__ out)          // (B, T, SD)
{
    __shared__ float AT[SD * SD];
    __shared__ float KT[OD * SD];
    __shared__ float xs[BPC][SD + 1];
    __shared__ float zs[BPC][OD];

    const int tid  = threadIdx.x;
    const int bl   = tid >> 5;
    const int lane = tid & 31;
    const int b    = blockIdx.x * BPC + bl;

    xs[bl][lane] = x0[b * SD + lane];
    // first __syncthreads inside the loop makes this visible

    for (int t = 0; t < TT; t++) {
        const float* __restrict__ at = g_AT[t];
        const float* __restrict__ kt = g_KT[t];
        for (int e = tid; e < SD * SD; e += BPC * 32) AT[e] = at[e];
        for (int e = tid; e < OD * SD; e += BPC * 32) KT[e] = kt[e];
        if (lane < OD) zs[bl][lane] = meas[(b * TT + t) * OD + lane];
        __syncthreads();

        float a0 = 0.f, a1 = 0.f;
        #pragma unroll
        for (int j = 0; j < SD; j += 2) {
            a0 += AT[j * SD + lane]       * xs[bl][j];
            a1 += AT[(j + 1) * SD + lane] * xs[bl][j + 1];
        }
        #pragma unroll
        for (int o = 0; o < OD; o += 2) {
            a0 += KT[o * SD + lane]       * zs[bl][o];
            a1 += KT[(o + 1) * SD + lane] * zs[bl][o + 1];
        }
        const float x = a0 + a1;
        out[(b * TT + t) * SD + lane] = x;
        __syncthreads();   // all reads of xs/AT/KT done before overwrite
        xs[bl][lane] = x;
    }
}

// ---------------------------------------------------------------------------
// Launch
// ---------------------------------------------------------------------------
extern "C" void kernel_launch(void* const* d_in, const int* in_sizes, int n_in,
                              void* d_out, int out_size) {
    const float* state0 = (const float*)d_in[0];  // (B, 32)
    const float* cov0   = (const float*)d_in[1];  // (B, 32, 32) -- identical per batch
    const float* meas   = (const float*)d_in[2];  // (B, 64, 16)
    const float* F      = (const float*)d_in[3];  // (32, 32)
    const float* H      = (const float*)d_in[4];  // (16, 32)
    const float* Q      = (const float*)d_in[5];  // (32, 32)
    const float* R      = (const float*)d_in[6];  // (16, 16)
    float* out = (float*)d_out;                   // (B, 64, 32)

    (void)in_sizes; (void)n_in; (void)out_size;

    phase1_kernel<<<1, 768>>>(F, H, Q, R, cov0);
    phase2_kernel<<<NB / BPC, BPC * 32>>>(state0, meas, out);
}

// round 3
// speedup vs baseline: 2.0128x; 2.0128x over previous
#include <cuda_runtime.h>

// Kalman filter B=2048, T=64, STATE=32, OBS=16.
// Phase 1 (1 CTA): batch-independent Riccati recursion -> per-step W_t = [A_t^T ; K_t^T].
// Phase 2 (256 CTAs): per-batch linear recursion x_t = A_t x_{t-1} + K_t z_t.

#define SD 32
#define OD 16
#define TT 64
#define NB 2048
#define P32 33
#define P16 17
#define BPC 8

// W_t layout: rows 0..31: W[j][i] = A_t[i][j]; rows 32..47: W[32+o][i] = K_t[i][o]
__device__ __align__(16) float g_W[TT][48 * SD];

// ---------------------------------------------------------------------------
// Phase 1
// ---------------------------------------------------------------------------
__global__ void __launch_bounds__(256, 1) phase1_kernel(
    const float* __restrict__ Fg,
    const float* __restrict__ Hg,
    const float* __restrict__ Qg,
    const float* __restrict__ Rg,
    const float* __restrict__ cov0)
{
    __shared__ float Fs[SD * P32];   // F row-major
    __shared__ float FT[SD * P32];   // F^T: FT[j][i] = F[i][j]
    __shared__ float Qs[SD * P32];
    __shared__ float Hs[OD * P32];   // H row-major
    __shared__ float Rs[OD * P16];
    __shared__ float Gs[OD * P32];   // G = H@F row-major: Gs[o][j]
    __shared__ float Ps[SD * P32];   // filtered covariance
    __shared__ float Pp[SD * P32];   // predicted covariance
    __shared__ float T1[SD * P32];   // temp (general-F path only)
    __shared__ float HPs[OD * P32];  // H @ Pp
    __shared__ float aug[OD * 49];   // [S | HP] -> [I | K^T]
    __shared__ int fid;

    const int tid = threadIdx.x;

    if (tid == 0) fid = 1;
    __syncthreads();

    {
        bool ok = true;
        #pragma unroll
        for (int s = 0; s < 4; s++) {
            int e = tid + s * 256;
            int i = e >> 5, j = e & 31;
            float f = Fg[e];
            Fs[i * P32 + j] = f;
            FT[j * P32 + i] = f;
            Qs[i * P32 + j] = Qg[e];
            Ps[i * P32 + j] = cov0[e];
            if (f != ((i == j) ? 1.0f : 0.0f)) ok = false;
        }
        if (!ok) fid = 0;
        #pragma unroll
        for (int s = 0; s < 2; s++) {
            int e = tid + s * 256;
            Hs[(e >> 5) * P32 + (e & 31)] = Hg[e];
        }
        Rs[(tid >> 4) * P16 + (tid & 15)] = Rg[tid];
    }
    __syncthreads();

    // G[o][j] = sum_k H[o][k] F[k][j]
    #pragma unroll
    for (int s = 0; s < 2; s++) {
        int e = tid + s * 256;           // 512 = 16*32
        int o = e >> 5, j = e & 31;
        float acc = 0.f;
        #pragma unroll
        for (int k = 0; k < SD; k++) acc += Hs[o * P32 + k] * FT[j * P32 + k];
        Gs[o * P32 + j] = acc;
    }
    const int ident = fid;
    __syncthreads();

    #pragma unroll 1
    for (int t = 0; t < TT; t++) {
        // ---- predict: Pp = F P F^T + Q ----
        if (ident) {
            #pragma unroll
            for (int s = 0; s < 4; s++) {
                int e = tid + s * 256;
                int idx = (e >> 5) * P32 + (e & 31);
                Pp[idx] = Ps[idx] + Qs[idx];
            }
        } else {
            #pragma unroll
            for (int s = 0; s < 4; s++) {
                int e = tid + s * 256;
                int i = e >> 5, j = e & 31;
                float acc = 0.f;
                #pragma unroll
                for (int k = 0; k < SD; k++) acc += Fs[i * P32 + k] * Ps[k * P32 + j];
                T1[i * P32 + j] = acc;
            }
            __syncthreads();
            #pragma unroll
            for (int s = 0; s < 4; s++) {
                int e = tid + s * 256;
                int i = e >> 5, j = e & 31;
                float acc = Qs[i * P32 + j];
                #pragma unroll
                for (int k = 0; k < SD; k++) acc += T1[i * P32 + k] * Fs[j * P32 + k];
                Pp[i * P32 + j] = acc;
            }
        }
        __syncthreads();

        // ---- HP[r][j] = sum_k H[r][k] Pp[k][j] ----
        #pragma unroll
        for (int s = 0; s < 2; s++) {
            int e = tid + s * 256;       // 512 = 16*32
            int r = e >> 5, j = e & 31;
            float acc = 0.f;
            #pragma unroll
            for (int k = 0; k < SD; k++) acc += Hs[r * P32 + k] * Pp[k * P32 + j];
            HPs[r * P32 + j] = acc;
        }
        __syncthreads();

        // ---- aug = [S | HP], S = HP H^T + R ----
        for (int e = tid; e < 768; e += 256) {
            int r = e / 48, c = e % 48;
            float v;
            if (c < OD) {
                v = Rs[r * P16 + c];
                #pragma unroll
                for (int k = 0; k < SD; k++) v += HPs[r * P32 + k] * Hs[c * P32 + k];
            } else {
                v = HPs[r * P32 + (c - OD)];
            }
            aug[r * 49 + c] = v;
        }
        __syncthreads();

        // ---- Gauss-Jordan, in place, full width (S SPD, no pivoting) ----
        #pragma unroll 1
        for (int p = 0; p < OD; p++) {
            float piv = aug[p * 49 + p];
            float pr[3], pc[3], vv[3];
            #pragma unroll
            for (int s = 0; s < 3; s++) {
                int e = tid + s * 256;
                int r = e / 48, c = e % 48;
                pr[s] = aug[p * 49 + c];
                pc[s] = aug[r * 49 + p];
                vv[s] = aug[r * 49 + c];
            }
            __syncthreads();
            float rinv = 1.0f / piv;
            #pragma unroll
            for (int s = 0; s < 3; s++) {
                int e = tid + s * 256;
                int r = e / 48, c = e % 48;
                float prn = pr[s] * rinv;
                aug[r * 49 + c] = (r == p) ? prn : (vv[s] - pc[s] * prn);
            }
            __syncthreads();
        }
        // K[i][o] = aug[o*49 + 16 + i]

        // ---- W rows 0..31 (A^T): W[j][i] = F[i][j] - sum_o G[o][j] K[i][o] ----
        #pragma unroll
        for (int s = 0; s < 4; s++) {
            int e = tid + s * 256;
            int j = e >> 5, i = e & 31;
            float w = FT[j * P32 + i];
            #pragma unroll
            for (int o = 0; o < OD; o++) w -= Gs[o * P32 + j] * aug[o * 49 + 16 + i];
            g_W[t][j * SD + i] = w;
        }
        // ---- W rows 32..47 (K^T) ----
        #pragma unroll
        for (int s = 0; s < 2; s++) {
            int e = tid + s * 256;       // 512 = 16*32
            int o = e >> 5, i = e & 31;
            g_W[t][(SD + o) * SD + i] = aug[o * 49 + 16 + i];
        }
        // ---- P_new = Pp - K @ HP ----
        #pragma unroll
        for (int s = 0; s < 4; s++) {
            int e = tid + s * 256;
            int i = e >> 5, j = e & 31;
            float pn = Pp[i * P32 + j];
            #pragma unroll
            for (int o = 0; o < OD; o++) pn -= aug[o * 49 + 16 + i] * HPs[o * P32 + j];
            Ps[i * P32 + j] = pn;
        }
        __syncthreads();
    }
}

// ---------------------------------------------------------------------------
// Phase 2: round-1 verified structure (smem xs/zs, 1 batch/warp, 2 syncs/step)
// + double-buffered W staging with register prefetch (float4).
// ---------------------------------------------------------------------------
__global__ void __launch_bounds__(BPC * 32, 1) phase2_kernel(
    const float* __restrict__ x0g,
    const float* __restrict__ meas,   // (B, T, 16)
    float* __restrict__ out)          // (B, T, 32)
{
    __shared__ float Wb[2][48 * SD];  // rows 0..31 = A^T, rows 32..47 = K^T
    __shared__ float xs[BPC][SD + 1];
    __shared__ float zs[BPC][OD];

    const int tid  = threadIdx.x;
    const int bl   = tid >> 5;
    const int lane = tid & 31;
    const int b    = blockIdx.x * BPC + bl;

    // prologue: state, z_0, W_0
    xs[bl][lane] = x0g[b * SD + lane];
    if (lane < OD) zs[bl][lane] = meas[(b * TT + 0) * OD + lane];
    {
        const float4* gw = (const float4*)g_W[0];
        float4* d = (float4*)Wb[0];
        d[tid] = gw[tid];
        if (tid < 128) d[256 + tid] = gw[256 + tid];
    }
    __syncthreads();

    #pragma unroll 1
    for (int t = 0; t < TT; t++) {
        // prefetch W_{t+1} into registers (no smem hazard)
        float4 n0, n1;
        if (t + 1 < TT) {
            const float4* gw = (const float4*)g_W[t + 1];
            n0 = gw[tid];
            if (tid < 128) n1 = gw[256 + tid];
        }

        const float* AT = Wb[t & 1];
        const float* KT = Wb[t & 1] + SD * SD;
        float a0 = 0.f, a1 = 0.f;
        #pragma unroll
        for (int j = 0; j < SD; j += 2) {
            a0 += AT[j * SD + lane]       * xs[bl][j];
            a1 += AT[(j + 1) * SD + lane] * xs[bl][j + 1];
        }
        #pragma unroll
        for (int o = 0; o < OD; o += 2) {
            a0 += KT[o * SD + lane]       * zs[bl][o];
            a1 += KT[(o + 1) * SD + lane] * zs[bl][o + 1];
        }
        const float x = a0 + a1;
        out[(b * TT + t) * SD + lane] = x;
        __syncthreads();   // all reads of xs/zs/Wb[t&1] complete

        xs[bl][lane] = x;
        if (t + 1 < TT) {
            if (lane < OD) zs[bl][lane] = meas[(b * TT + (t + 1)) * OD + lane];
            float4* d = (float4*)Wb[(t + 1) & 1];
            d[tid] = n0;
            if (tid < 128) d[256 + tid] = n1;
        }
        __syncthreads();   // xs, zs, W_{t+1} visible for next iteration
    }
}

// ---------------------------------------------------------------------------
extern "C" void kernel_launch(void* const* d_in, const int* in_sizes, int n_in,
                              void* d_out, int out_size) {
    const float* state0 = (const float*)d_in[0];  // (B, 32)
    const float* cov0   = (const float*)d_in[1];  // (B, 32, 32) identical per batch
    const float* meas   = (const float*)d_in[2];  // (B, 64, 16)
    const float* F      = (const float*)d_in[3];  // (32, 32)
    const float* H      = (const float*)d_in[4];  // (16, 32)
    const float* Q      = (const float*)d_in[5];  // (32, 32)
    const float* R      = (const float*)d_in[6];  // (16, 16)
    float* out = (float*)d_out;                   // (B, 64, 32)
    (void)in_sizes; (void)n_in; (void)out_size;

    phase1_kernel<<<1, 256>>>(F, H, Q, R, cov0);
    phase2_kernel<<<NB / BPC, BPC * 32>>>(state0, meas, out);
}